// round 4
// baseline (speedup 1.0000x reference)
#include <cuda_runtime.h>
#include <math.h>

#define FDIM 128
#define HDIM 32
#define NN_MAX 100000
#define NE_MAX 3200000
#define NGRAPH 512

// ---- scratch (no allocation allowed) ----
__device__ __align__(128) float g_tA[NN_MAX * HDIM];
__device__ __align__(128) float g_tB[NN_MAX * HDIM];
__device__ __align__(128) float g_pool[NGRAPH * HDIM];
__device__ __align__(128) int   g_deg[NN_MAX + 1];     // then holds nothing; off separate
__device__ __align__(128) int   g_off[NN_MAX + 1];
__device__ __align__(128) int   g_cursor[NN_MAX];
__device__ __align__(128) int   g_ecol[NE_MAX];
__device__ __align__(128) float g_ew[NE_MAX];

// ---------------------------------------------------------------------------
// CSR build step 1: degree histogram
// ---------------------------------------------------------------------------
__global__ void hist_kernel(const int* __restrict__ row, int* __restrict__ deg, int E) {
    int e0 = (blockIdx.x * blockDim.x + threadIdx.x) * 4;
    if (e0 + 3 < E) {
        int4 r = *(const int4*)(row + e0);
        atomicAdd(&deg[r.x], 1);
        atomicAdd(&deg[r.y], 1);
        atomicAdd(&deg[r.z], 1);
        atomicAdd(&deg[r.w], 1);
    } else {
        for (int e = e0; e < E; e++) atomicAdd(&deg[row[e]], 1);
    }
}

// ---------------------------------------------------------------------------
// CSR build step 2: exclusive scan (single block, 1024 threads, warp-shuffle)
// ---------------------------------------------------------------------------
__global__ void scan_kernel(const int* __restrict__ deg, int* __restrict__ off,
                            int* __restrict__ cursor, int N) {
    __shared__ int warp_sums[32];
    __shared__ int s_carry;
    int tid = threadIdx.x;
    int lane = tid & 31, wid = tid >> 5;
    if (tid == 0) s_carry = 0;
    __syncthreads();

    for (int base = 0; base < N; base += 1024) {
        int i = base + tid;
        int v = (i < N) ? deg[i] : 0;
        int x = v;                                  // inclusive warp scan
#pragma unroll
        for (int d = 1; d < 32; d <<= 1) {
            int y = __shfl_up_sync(0xffffffffu, x, d);
            if (lane >= d) x += y;
        }
        if (lane == 31) warp_sums[wid] = x;
        __syncthreads();
        if (wid == 0) {
            int ws = warp_sums[lane];
            int xs = ws;
#pragma unroll
            for (int d = 1; d < 32; d <<= 1) {
                int y = __shfl_up_sync(0xffffffffu, xs, d);
                if (lane >= d) xs += y;
            }
            warp_sums[lane] = xs - ws;              // exclusive warp offsets
        }
        __syncthreads();
        int excl = s_carry + warp_sums[wid] + (x - v);
        if (i < N) { off[i] = excl; cursor[i] = excl; }
        __syncthreads();                            // everyone has read s_carry
        if (tid == 1023) s_carry = excl + v;        // += chunk total
        __syncthreads();
    }
    if (threadIdx.x == 0) off[N] = s_carry;
}

// ---------------------------------------------------------------------------
// CSR build step 3: scatter edges into row-grouped arrays
// ---------------------------------------------------------------------------
__global__ void scatter_kernel(const int* __restrict__ row, const int* __restrict__ col,
                               const float* __restrict__ w,
                               int* __restrict__ cursor,
                               int* __restrict__ ecol, float* __restrict__ ew, int E) {
    int e = blockIdx.x * blockDim.x + threadIdx.x;
    if (e >= E) return;
    int r = row[e];
    int pos = atomicAdd(&cursor[r], 1);
    ecol[pos] = col[e];
    ew[pos]   = w[e];
}

// ---------------------------------------------------------------------------
// GEMM1: t = x @ W1   ([N,128] @ [128,32])
// ---------------------------------------------------------------------------
__global__ void gemm1_kernel(const float* __restrict__ x,
                             const float* __restrict__ W,
                             float* __restrict__ t, int N) {
    __shared__ float sW[FDIM * HDIM];
    __shared__ float sx[8 * FDIM];
    int tid = threadIdx.x;
    for (int i = tid; i < FDIM * HDIM; i += blockDim.x) sW[i] = W[i];
    int warp = tid >> 5, lane = tid & 31;

    for (long base = (long)blockIdx.x * 8; base < N; base += (long)gridDim.x * 8) {
        int nrows = (int)min((long)8, (long)N - base);
        __syncthreads();
        int nquads = nrows * (FDIM / 4);
        const float4* src = (const float4*)(x + base * FDIM);
        for (int i = tid; i < nquads; i += blockDim.x)
            ((float4*)sx)[i] = src[i];
        __syncthreads();
        if (warp < nrows) {
            const float* xr = sx + warp * FDIM;
            float a = 0.f;
#pragma unroll 16
            for (int k = 0; k < FDIM; k++)
                a += xr[k] * sW[k * HDIM + lane];
            t[(base + warp) * HDIM + lane] = a;
        }
    }
}

// ---------------------------------------------------------------------------
// Fused layer: for node n (one warp, lane = channel):
//   a = sum_{e in row n} w_e * tin[col_e]        (CSR gather, registers)
//   h = elu(a + b[lane])
//   tout[n] = h @ Wnext                          (shuffle GEMM 32x32)
// ---------------------------------------------------------------------------
__global__ void spmm_fused_kernel(const int* __restrict__ off,
                                  const int* __restrict__ ecol,
                                  const float* __restrict__ ew,
                                  const float* __restrict__ tin,
                                  const float* __restrict__ b,
                                  const float* __restrict__ W,
                                  float* __restrict__ tout, int N) {
    __shared__ float sW[HDIM * HDIM];
    __shared__ float sb[HDIM];
    int tid = threadIdx.x;
    for (int i = tid; i < HDIM * HDIM; i += blockDim.x) sW[i] = W[i];
    if (tid < HDIM) sb[tid] = b[tid];
    __syncthreads();

    int lane = tid & 31;
    int n = (blockIdx.x * blockDim.x + tid) >> 5;
    if (n >= N) return;

    int s = off[n], e1 = off[n + 1];
    float a = 0.f;
    for (int e = s; e < e1; e += 32) {
        int cnt = e1 - e;                       // >=1
        int c = 0; float wv = 0.f;
        if (lane < cnt) { c = ecol[e + lane]; wv = ew[e + lane]; }
#pragma unroll
        for (int j = 0; j < 32; j++) {
            int   cj = __shfl_sync(0xffffffffu, c,  j);
            float wj = __shfl_sync(0xffffffffu, wv, j);
            a += wj * tin[cj * HDIM + lane];    // padded lanes: wj=0, cj=0 (safe)
        }
    }
    float v = a + sb[lane];
    v = v > 0.f ? v : (expf(v) - 1.f);          // ELU
    float o = 0.f;
#pragma unroll
    for (int k = 0; k < HDIM; k++)
        o += __shfl_sync(0xffffffffu, v, k) * sW[k * HDIM + lane];
    tout[n * HDIM + lane] = o;
}

// ---------------------------------------------------------------------------
// Final layer fused with pool: a = spmm row; h = elu(a+b3); pool[seg[n]] += h
// ---------------------------------------------------------------------------
__global__ void spmm_pool_kernel(const int* __restrict__ off,
                                 const int* __restrict__ ecol,
                                 const float* __restrict__ ew,
                                 const float* __restrict__ tin,
                                 const float* __restrict__ b,
                                 const int* __restrict__ seg,
                                 float* __restrict__ pool, int N) {
    int tid = threadIdx.x;
    int lane = tid & 31;
    int n = (blockIdx.x * blockDim.x + tid) >> 5;
    if (n >= N) return;

    int s = off[n], e1 = off[n + 1];
    float a = 0.f;
    for (int e = s; e < e1; e += 32) {
        int cnt = e1 - e;
        int c = 0; float wv = 0.f;
        if (lane < cnt) { c = ecol[e + lane]; wv = ew[e + lane]; }
#pragma unroll
        for (int j = 0; j < 32; j++) {
            int   cj = __shfl_sync(0xffffffffu, c,  j);
            float wj = __shfl_sync(0xffffffffu, wv, j);
            a += wj * tin[cj * HDIM + lane];
        }
    }
    float v = a + b[lane];
    v = v > 0.f ? v : (expf(v) - 1.f);
    atomicAdd(&pool[seg[n] * HDIM + lane], v);  // REDG, 16K distinct addrs
}

// ---------------------------------------------------------------------------
// MLP head
// ---------------------------------------------------------------------------
__global__ void mlp_kernel(const float* __restrict__ pool,
                           const float* __restrict__ W1, const float* __restrict__ b1,
                           const float* __restrict__ W2, const float* __restrict__ b2,
                           const float* __restrict__ W3, const float* __restrict__ b3,
                           float* __restrict__ out) {
    __shared__ float sW1[32 * 64], sW2[64 * 32], sW3[32], sb1[64], sb2[32];
    int tid = threadIdx.x;
    for (int i = tid; i < 2048; i += blockDim.x) { sW1[i] = W1[i]; sW2[i] = W2[i]; }
    if (tid < 64) sb1[tid] = b1[tid];
    if (tid < 32) { sW3[tid] = W3[tid]; sb2[tid] = b2[tid]; }
    __syncthreads();

    int g = blockIdx.x * blockDim.x + tid;
    if (g >= NGRAPH) return;
    float in[32];
#pragma unroll
    for (int c = 0; c < 32; c++) in[c] = pool[g * 32 + c];
    float h2[32];
#pragma unroll
    for (int c = 0; c < 32; c++) h2[c] = sb2[c];
    for (int j = 0; j < 64; j++) {
        float tacc = sb1[j];
#pragma unroll
        for (int c = 0; c < 32; c++) tacc += in[c] * sW1[c * 64 + j];
        tacc = fmaxf(tacc, 0.f);
#pragma unroll
        for (int c = 0; c < 32; c++) h2[c] += tacc * sW2[j * 32 + c];
    }
    float o = b3[0];
#pragma unroll
    for (int c = 0; c < 32; c++) o += fmaxf(h2[c], 0.f) * sW3[c];
    out[g] = 1.f / (1.f + expf(-o));
}

// ---------------------------------------------------------------------------
extern "C" void kernel_launch(void* const* d_in, const int* in_sizes, int n_in,
                              void* d_out, int out_size) {
    const float* x   = (const float*)d_in[0];
    const int*   ei  = (const int*)  d_in[1];
    const float* ew  = (const float*)d_in[2];
    const int*   seg = (const int*)  d_in[3];
    const float* W1  = (const float*)d_in[4];
    const float* b1  = (const float*)d_in[5];
    const float* W2  = (const float*)d_in[6];
    const float* b2  = (const float*)d_in[7];
    const float* W3  = (const float*)d_in[8];
    const float* b3  = (const float*)d_in[9];
    const float* Wd1 = (const float*)d_in[10];
    const float* bd1 = (const float*)d_in[11];
    const float* Wd2 = (const float*)d_in[12];
    const float* bd2 = (const float*)d_in[13];
    const float* Wd3 = (const float*)d_in[14];
    const float* bd3 = (const float*)d_in[15];
    float* out = (float*)d_out;

    int N = in_sizes[0] / FDIM;
    int E = in_sizes[1] / 2;
    const int* row = ei;
    const int* col = ei + E;

    float *tA, *tB, *pool, *gew;
    int *deg, *off, *cursor, *gecol;
    cudaGetSymbolAddress((void**)&tA,     g_tA);
    cudaGetSymbolAddress((void**)&tB,     g_tB);
    cudaGetSymbolAddress((void**)&pool,   g_pool);
    cudaGetSymbolAddress((void**)&deg,    g_deg);
    cudaGetSymbolAddress((void**)&off,    g_off);
    cudaGetSymbolAddress((void**)&cursor, g_cursor);
    cudaGetSymbolAddress((void**)&gecol,  g_ecol);
    cudaGetSymbolAddress((void**)&gew,    g_ew);

    int warpBlocks = (N * 32 + 255) / 256;

    // ---- CSR build (amortized over 3 layers) ----
    cudaMemsetAsync(deg, 0, (size_t)(N + 1) * sizeof(int));
    hist_kernel<<<(E / 4 + 255) / 256 + 1, 256>>>(row, deg, E);
    scan_kernel<<<1, 1024>>>(deg, off, cursor, N);
    scatter_kernel<<<(E + 255) / 256, 256>>>(row, col, ew, cursor, gecol, gew, E);

    // ---- GCN layers ----
    gemm1_kernel<<<1480, 256>>>(x, W1, tA, N);
    spmm_fused_kernel<<<warpBlocks, 256>>>(off, gecol, gew, tA, b1, W2, tB, N);
    spmm_fused_kernel<<<warpBlocks, 256>>>(off, gecol, gew, tB, b2, W3, tA, N);

    // ---- final layer + pool + head ----
    cudaMemsetAsync(pool, 0, (size_t)NGRAPH * HDIM * sizeof(float));
    spmm_pool_kernel<<<warpBlocks, 256>>>(off, gecol, gew, tA, b3, seg, pool, N);
    mlp_kernel<<<2, 256>>>(pool, Wd1, bd1, Wd2, bd2, Wd3, bd3, out);
}

// round 6
// speedup vs baseline: 1.3259x; 1.3259x over previous
#include <cuda_runtime.h>
#include <math.h>

#define FDIM 128
#define HDIM 32
#define NN_MAX 100000
#define NGRAPH 512

// Scratch (no allocation allowed)
__device__ __align__(128) float g_h[NN_MAX * HDIM];
__device__ __align__(128) float g_acc[NN_MAX * HDIM];
__device__ __align__(128) float g_pool[NGRAPH * HDIM];

// ---------------------------------------------------------------------------
// GEMM1: h = x @ W1   ([N,128] @ [128,32])
// Block 256 = 8 warps; block tile = 64 rows. Warp computes 8 rows.
// Inner loop blocked 4-wide in k: 4 scalar sW loads (conflict-free) +
// 8 broadcast LDS.128 x loads + 32 FMA per (4k x 8rows) step.
// ---------------------------------------------------------------------------
__global__ void gemm1_kernel(const float* __restrict__ x,
                             const float* __restrict__ W,
                             float* __restrict__ h, int N) {
    __shared__ float sW[FDIM * HDIM];   // 16 KB
    __shared__ float sx[64 * FDIM];     // 32 KB (total 48 KB)
    int tid = threadIdx.x;
    int warp = tid >> 5, lane = tid & 31;
    for (int i = tid; i < FDIM * HDIM; i += 256) sW[i] = W[i];

    for (long base = (long)blockIdx.x * 64; base < N; base += (long)gridDim.x * 64) {
        int nrows = (int)min((long)64, (long)N - base);
        __syncthreads();
        int nquads = nrows * (FDIM / 4);
        const float4* src = (const float4*)(x + base * FDIM);
        for (int i = tid; i < nquads; i += 256)
            ((float4*)sx)[i] = src[i];
        __syncthreads();

        int r0 = warp * 8;
        float a[8] = {0.f, 0.f, 0.f, 0.f, 0.f, 0.f, 0.f, 0.f};
        const float* xb = sx + r0 * FDIM;
#pragma unroll 4
        for (int k = 0; k < FDIM; k += 4) {
            float w0 = sW[(k + 0) * HDIM + lane];
            float w1 = sW[(k + 1) * HDIM + lane];
            float w2 = sW[(k + 2) * HDIM + lane];
            float w3 = sW[(k + 3) * HDIM + lane];
#pragma unroll
            for (int r = 0; r < 8; r++) {
                float4 xq = *(const float4*)(xb + r * FDIM + k);  // broadcast LDS.128
                a[r] += xq.x * w0 + xq.y * w1 + xq.z * w2 + xq.w * w3;
            }
        }
#pragma unroll
        for (int r = 0; r < 8; r++) {
            if (r0 + r < nrows)
                h[(base + r0 + r) * HDIM + lane] = a[r];
        }
    }
}

// ---------------------------------------------------------------------------
// Fused  h_out = (elu(acc + b)) @ W   ([N,32] @ [32,32])
// Warp per node: lane holds elu(acc[n][lane]+b[lane]); shuffle-broadcast GEMM.
// ---------------------------------------------------------------------------
__global__ void gemm_elu_kernel(const float* __restrict__ acc_in,
                                const float* __restrict__ b,
                                const float* __restrict__ W,
                                float* __restrict__ h, int N) {
    __shared__ float sW[HDIM * HDIM];
    __shared__ float sb[HDIM];
    int tid = threadIdx.x;
    for (int i = tid; i < HDIM * HDIM; i += blockDim.x) sW[i] = W[i];
    if (tid < HDIM) sb[tid] = b[tid];
    __syncthreads();

    int lane = tid & 31;
    int gwarp = (blockIdx.x * blockDim.x + tid) >> 5;
    int nwarps = (gridDim.x * blockDim.x) >> 5;
    for (int n = gwarp; n < N; n += nwarps) {
        float v = acc_in[n * HDIM + lane] + sb[lane];
        v = v > 0.f ? v : (expf(v) - 1.f);     // ELU (alpha=1)
        float o = 0.f;
#pragma unroll
        for (int k = 0; k < HDIM; k++)
            o += __shfl_sync(0xffffffffu, v, k) * sW[k * HDIM + lane];
        h[n * HDIM + lane] = o;
    }
}

// ---------------------------------------------------------------------------
// SpMM: acc[row] += w * h[col]   (32-wide rows)
// 8 lanes per group of 4 consecutive edges: vector metadata loads,
// 4 independent float4 gathers (MLP=4), 4x red.global.add.v4.f32.
// ---------------------------------------------------------------------------
__device__ __forceinline__ void red4(float* rowp, int l, float4 v, float s) {
    float4* dst = (float4*)rowp + l;
    asm volatile("red.global.add.v4.f32 [%0], {%1,%2,%3,%4};"
                 :: "l"(__cvta_generic_to_global(dst)),
                    "f"(v.x * s), "f"(v.y * s), "f"(v.z * s), "f"(v.w * s)
                 : "memory");
}

__global__ void spmm_kernel(const int* __restrict__ row,
                            const int* __restrict__ col,
                            const float* __restrict__ w,
                            const float* __restrict__ h,
                            float* __restrict__ acc, int E) {
    int t = blockIdx.x * blockDim.x + threadIdx.x;
    int g = t >> 3;        // group id: 4 edges per group
    int l = t & 7;
    int e0 = g << 2;
    if (e0 >= E) return;

    const float4* h4 = (const float4*)h;
    if (e0 + 3 < E) {
        int4   r  = *(const int4*)(row + e0);
        int4   c  = *(const int4*)(col + e0);
        float4 wt = *(const float4*)(w + e0);
        float4 v0 = h4[c.x * 8 + l];
        float4 v1 = h4[c.y * 8 + l];
        float4 v2 = h4[c.z * 8 + l];
        float4 v3 = h4[c.w * 8 + l];
        red4(acc + r.x * HDIM, l, v0, wt.x);
        red4(acc + r.y * HDIM, l, v1, wt.y);
        red4(acc + r.z * HDIM, l, v2, wt.z);
        red4(acc + r.w * HDIM, l, v3, wt.w);
    } else {
        for (int e = e0; e < E; e++) {
            float4 v = h4[col[e] * 8 + l];
            red4(acc + row[e] * HDIM, l, v, w[e]);
        }
    }
}

// ---------------------------------------------------------------------------
// Pool: pool[seg[n]][c] += elu(acc[n][c] + b[c])
// ---------------------------------------------------------------------------
__global__ void pool_kernel(const float* __restrict__ acc,
                            const float* __restrict__ b,
                            const int* __restrict__ seg,
                            float* __restrict__ pool, int N) {
    int idx = blockIdx.x * blockDim.x + threadIdx.x;
    if (idx >= N * HDIM) return;
    int n = idx >> 5, c = idx & 31;
    float v = acc[idx] + b[c];
    v = v > 0.f ? v : (expf(v) - 1.f);
    atomicAdd(&pool[seg[n] * HDIM + c], v);   // ptxas -> REDG (no return)
}

// ---------------------------------------------------------------------------
// MLP head: out = sigmoid(relu(relu(pool@Wd1+bd1)@Wd2+bd2)@Wd3+bd3)
// ---------------------------------------------------------------------------
__global__ void mlp_kernel(const float* __restrict__ pool,
                           const float* __restrict__ W1, const float* __restrict__ b1,
                           const float* __restrict__ W2, const float* __restrict__ b2,
                           const float* __restrict__ W3, const float* __restrict__ b3,
                           float* __restrict__ out) {
    __shared__ float sW1[32 * 64], sW2[64 * 32], sW3[32], sb1[64], sb2[32];
    int tid = threadIdx.x;
    for (int i = tid; i < 2048; i += blockDim.x) { sW1[i] = W1[i]; sW2[i] = W2[i]; }
    if (tid < 64) sb1[tid] = b1[tid];
    if (tid < 32) { sW3[tid] = W3[tid]; sb2[tid] = b2[tid]; }
    __syncthreads();

    int g = blockIdx.x * blockDim.x + tid;
    if (g >= NGRAPH) return;
    float in[32];
#pragma unroll
    for (int c = 0; c < 32; c++) in[c] = pool[g * 32 + c];
    float h2[32];
#pragma unroll
    for (int c = 0; c < 32; c++) h2[c] = sb2[c];
    for (int j = 0; j < 64; j++) {
        float t = sb1[j];
#pragma unroll
        for (int c = 0; c < 32; c++) t += in[c] * sW1[c * 64 + j];
        t = fmaxf(t, 0.f);
#pragma unroll
        for (int c = 0; c < 32; c++) h2[c] += t * sW2[j * 32 + c];
    }
    float o = b3[0];
#pragma unroll
    for (int c = 0; c < 32; c++) o += fmaxf(h2[c], 0.f) * sW3[c];
    out[g] = 1.f / (1.f + expf(-o));
}

// ---------------------------------------------------------------------------
extern "C" void kernel_launch(void* const* d_in, const int* in_sizes, int n_in,
                              void* d_out, int out_size) {
    const float* x   = (const float*)d_in[0];
    const int*   ei  = (const int*)  d_in[1];
    const float* ew  = (const float*)d_in[2];
    const int*   seg = (const int*)  d_in[3];
    const float* W1  = (const float*)d_in[4];
    const float* b1  = (const float*)d_in[5];
    const float* W2  = (const float*)d_in[6];
    const float* b2  = (const float*)d_in[7];
    const float* W3  = (const float*)d_in[8];
    const float* b3  = (const float*)d_in[9];
    const float* Wd1 = (const float*)d_in[10];
    const float* bd1 = (const float*)d_in[11];
    const float* Wd2 = (const float*)d_in[12];
    const float* bd2 = (const float*)d_in[13];
    const float* Wd3 = (const float*)d_in[14];
    const float* bd3 = (const float*)d_in[15];
    float* out = (float*)d_out;

    int N = in_sizes[0] / FDIM;
    int E = in_sizes[1] / 2;
    const int* row = ei;
    const int* col = ei + E;

    float *h, *acc, *pool;
    cudaGetSymbolAddress((void**)&h,    g_h);
    cudaGetSymbolAddress((void**)&acc,  g_acc);
    cudaGetSymbolAddress((void**)&pool, g_pool);

    size_t accBytes = (size_t)N * HDIM * sizeof(float);
    int nGroups = (E + 3) / 4;
    int spmmBlocks = (nGroups * 8 + 255) / 256;
    int gemm1Blocks = (N + 63) / 64;

    // Layer 1
    gemm1_kernel<<<gemm1Blocks, 256>>>(x, W1, h, N);
    cudaMemsetAsync(acc, 0, accBytes);
    spmm_kernel<<<spmmBlocks, 256>>>(row, col, ew, h, acc, E);

    // Layer 2 (fuses layer-1 bias+ELU)
    gemm_elu_kernel<<<1480, 256>>>(acc, b1, W2, h, N);
    cudaMemsetAsync(acc, 0, accBytes);
    spmm_kernel<<<spmmBlocks, 256>>>(row, col, ew, h, acc, E);

    // Layer 3 (fuses layer-2 bias+ELU)
    gemm_elu_kernel<<<1480, 256>>>(acc, b2, W3, h, N);
    cudaMemsetAsync(acc, 0, accBytes);
    spmm_kernel<<<spmmBlocks, 256>>>(row, col, ew, h, acc, E);

    // Pool (fuses layer-3 bias+ELU) + MLP head
    cudaMemsetAsync(pool, 0, (size_t)NGRAPH * HDIM * sizeof(float));
    pool_kernel<<<(N * HDIM + 255) / 256, 256>>>(acc, b3, seg, pool, N);
    mlp_kernel<<<2, 256>>>(pool, Wd1, bd1, Wd2, bd2, Wd3, bd3, out);
}